// round 2
// baseline (speedup 1.0000x reference)
#include <cuda_runtime.h>

// Locally-connected 2D: out[oy,ox] = sum_{ky,kx} x[oy+ky, ox+kx] * W[oy,ox,ky,kx]
// x: [450,450] f32, W: [436,436,15,15] f32 (171 MB, streamed once), out: [436,436] f32.
// HBM-bound. Warp-per-pixel for coalesced W; each warp handles 4 consecutive
// pixels in a row so the lane->patch-offset math is computed ONCE and all
// loads become pointer+immediate (no per-iteration ALU).

#define IN_H 450
#define IN_W 450
#define KH 15
#define KW 15
#define OH 436
#define OW 436
#define KSIZE (KH * KW)   // 225
#define NPIX (OH * OW)    // 190096
#define PPW 4             // pixels per warp (OW % PPW == 0 -> never crosses rows)

__global__ __launch_bounds__(256)
void lc2d_kernel(const float* __restrict__ x,
                 const float* __restrict__ W,
                 float* __restrict__ out)
{
    const int lane = threadIdx.x & 31;
    const int warp = (blockIdx.x * blockDim.x + threadIdx.x) >> 5;
    const int pix0 = warp * PPW;
    if (pix0 >= NPIX) return;

    const int oy = pix0 / OW;
    const int ox = pix0 - oy * OW;

    // Per-lane x pointers for k = lane + 32*i, i = 0..6 (k <= 223 < 225 always).
    // Computed once, reused for all PPW pixels.
    const float* xbase = x + oy * IN_W + ox;
    const float* xptr[7];
#pragma unroll
    for (int i = 0; i < 7; i++) {
        const int k  = lane + (i << 5);
        const int ky = k / KW;
        const int kx = k - ky * KW;
        xptr[i] = xbase + ky * IN_W + kx;
    }
    // Tail element k=224 (ky=14,kx=14) handled by lane 0 only.
    const float* xtail = xbase + 14 * IN_W + 14;

    const float* wbase = W + (size_t)pix0 * KSIZE + lane;

#pragma unroll
    for (int p = 0; p < PPW; p++) {
        const float* wp = wbase + p * KSIZE;   // +900B compile-time immediates
        float sum = 0.0f;
#pragma unroll
        for (int i = 0; i < 7; i++) {
            const float wv = __ldcs(wp + (i << 5));   // coalesced 128B, streaming
            const float xv = __ldg(xptr[i] + p);      // [Rptr + imm], L1/L2-hot
            sum = fmaf(wv, xv, sum);
        }
        if (lane == 0)
            sum = fmaf(__ldcs(wp + (224 - 0)), __ldg(xtail + p), sum);

        // Warp reduction
#pragma unroll
        for (int off = 16; off > 0; off >>= 1)
            sum += __shfl_down_sync(0xffffffffu, sum, off);

        if (lane == 0)
            out[pix0 + p] = sum;
    }
}

extern "C" void kernel_launch(void* const* d_in, const int* in_sizes, int n_in,
                              void* d_out, int out_size)
{
    const float* x = (const float*)d_in[0];
    const float* W = (const float*)d_in[1];
    float* out = (float*)d_out;

    const int threads = 256;                       // 8 warps/block
    const int pix_per_block = (threads / 32) * PPW; // 32
    const int blocks = (NPIX + pix_per_block - 1) / pix_per_block;

    lc2d_kernel<<<blocks, threads>>>(x, W, out);
}